// round 9
// baseline (speedup 1.0000x reference)
#include <cuda_runtime.h>
#include <cuda_fp16.h>

#define NS 3
#define NQ 64
#define NN (128*128*32)    // 524288
#define NN4 (NN/4)         // 131072 float4 per row
#define NW (NN/32)         // 16384 packed words per row
#define NC 21
#define IOU_T 0.2f
#define WCH 256
#define SROW (WCH+4)       // 260-word smem row stride

// ---------------- scratch (device globals; no allocation) ----------------
__device__ unsigned g_mask [NS*NQ*NW];
__device__ unsigned g_occ  [NW];
__device__ uint2    g_a1   [(size_t)NQ*NN4];   // merged anchor after iter1, fp16x4 (output path only)
__device__ int g_cnt [NS*NQ];
__device__ int g_cnt2[NQ];
__device__ int g_inter1[NQ*NQ];
__device__ int g_inter2[NQ*NQ];
__device__ int g_idx1[NQ], g_m1[NQ], g_idx2[NQ], g_m2[NQ], g_keep[NQ];
__device__ float g_iou1[NQ];

__device__ __forceinline__ float sigf(float x){ return 1.0f/(1.0f + __expf(-x)); }

__device__ __forceinline__ uint2 pack4h(float a, float b, float c, float d){
    __half2 h01 = __floats2half2_rn(a, b);
    __half2 h23 = __floats2half2_rn(c, d);
    uint2 r; r.x = *(unsigned*)&h01; r.y = *(unsigned*)&h23; return r;
}
__device__ __forceinline__ float4 unpack4h(uint2 hv){
    float2 a01 = __half22float2(*(__half2*)&hv.x);
    float2 a23 = __half22float2(*(__half2*)&hv.y);
    return make_float4(a01.x, a01.y, a23.x, a23.y);
}

// ---------------- zero accumulators ----------------
__global__ void init_kernel(){
    int t = blockIdx.x*256 + threadIdx.x;
    if (t < NQ*NQ){ g_inter1[t] = 0; g_inter2[t] = 0; }
    if (t < NS*NQ) g_cnt[t] = 0;
    if (t < NQ)    g_cnt2[t] = 0;
}

// ---------------- occupancy bits (pure streaming; side stream) ----------------
__global__ void occ_kernel(const float4* __restrict__ sem4){
    int f = blockIdx.x*256 + threadIdx.x;
    int lane = threadIdx.x & 31;
    float4 v0 = __ldcs(&sem4[f]);
    unsigned nib = 0;
    #pragma unroll
    for (int c = 1; c < NC; c++){
        float4 vc = __ldcs(&sem4[(size_t)c*NN4 + f]);
        nib |= (unsigned)(vc.x > v0.x) | ((unsigned)(vc.y > v0.y) << 1)
             | ((unsigned)(vc.z > v0.z) << 2) | ((unsigned)(vc.w > v0.w) << 3);
    }
    unsigned part = nib << ((lane & 7) * 4);
    part |= __shfl_xor_sync(~0u, part, 1);
    part |= __shfl_xor_sync(~0u, part, 2);
    part |= __shfl_xor_sync(~0u, part, 4);
    if ((lane & 7) == 0) g_occ[f >> 3] = part;
}

// ---------------- pass 1: pack (logit>0) bits; optional row counts (s=2) ----------------
__global__ void mask_kernel(const float4* __restrict__ vl4, int s_base, int do_cnt){
    int s = blockIdx.z + s_base, q = blockIdx.y;
    int row = s*NQ + q;
    size_t row4 = (size_t)row * NN4;
    size_t mrow = (size_t)row * NW;
    int t = threadIdx.x, lane = t & 31;
    int cnt = 0;
    #pragma unroll
    for (int j = 0; j < 4; j++){
        int f = blockIdx.x*1024 + j*256 + t;
        float4 v = __ldcs(&vl4[row4 + f]);
        unsigned nib = (unsigned)(v.x > 0.f) | ((unsigned)(v.y > 0.f) << 1)
                     | ((unsigned)(v.z > 0.f) << 2) | ((unsigned)(v.w > 0.f) << 3);
        unsigned part = nib << ((lane & 7) * 4);
        part |= __shfl_xor_sync(~0u, part, 1);
        part |= __shfl_xor_sync(~0u, part, 2);
        part |= __shfl_xor_sync(~0u, part, 4);
        if ((lane & 7) == 0){
            g_mask[mrow + (f >> 3)] = part;
            cnt += __popc(part);
        }
    }
    if (do_cnt){
        #pragma unroll
        for (int d = 16; d; d >>= 1) cnt += __shfl_xor_sync(~0u, cnt, d);
        __shared__ int sc[8];
        if (lane == 0) sc[t >> 5] = cnt;
        __syncthreads();
        if (t == 0){
            int tot = 0;
            #pragma unroll
            for (int k = 0; k < 8; k++) tot += sc[k];
            atomicAdd(&g_cnt[row], tot);
        }
    }
}

// ---------------- round-0 bit-popcount GEMM (s0 x s1) + fused row counts ----------------
__global__ void __launch_bounds__(256, 4) inter_kernel(){
    __shared__ unsigned sA[16*SROW];
    __shared__ unsigned sB[16*SROW];
    const unsigned* A = g_mask;
    const unsigned* B = g_mask + (size_t)NQ*NW;
    int w0 = blockIdx.x * WCH;
    int q0 = blockIdx.y * 16, p0 = blockIdx.z * 16;
    int t = threadIdx.x;
    for (int i = t; i < 16*64; i += 256){
        int r = i >> 6, c = (i & 63) * 4;
        *(uint4*)&sA[r*SROW + c] = *(const uint4*)&A[(size_t)(q0 + r)*NW + w0 + c];
        *(uint4*)&sB[r*SROW + c] = *(const uint4*)&B[(size_t)(p0 + r)*NW + w0 + c];
    }
    __syncthreads();
    if (blockIdx.z == 0){
        int r = t >> 4, part = t & 15;
        int c = 0;
        #pragma unroll
        for (int w = 0; w < 16; w++) c += __popc(sA[r*SROW + part*16 + w]);
        #pragma unroll
        for (int d = 8; d; d >>= 1) c += __shfl_down_sync(~0u, c, d, 16);
        if (part == 0) atomicAdd(&g_cnt[q0 + r], c);
    }
    if (blockIdx.y == 0){
        int r = t >> 4, part = t & 15;
        int c = 0;
        #pragma unroll
        for (int w = 0; w < 16; w++) c += __popc(sB[r*SROW + part*16 + w]);
        #pragma unroll
        for (int d = 8; d; d >>= 1) c += __shfl_down_sync(~0u, c, d, 16);
        if (part == 0) atomicAdd(&g_cnt[NQ + p0 + r], c);
    }
    int px = t & 3, qx = (t >> 2) & 3, ws = t >> 4;
    int acc[16];
    #pragma unroll
    for (int k = 0; k < 16; k++) acc[k] = 0;
    int wbeg = ws * 16;
    #pragma unroll
    for (int w = wbeg; w < wbeg + 16; w += 4){
        uint4 a[4], b[4];
        #pragma unroll
        for (int i = 0; i < 4; i++){
            a[i] = *(uint4*)&sA[(qx + 4*i)*SROW + w];
            b[i] = *(uint4*)&sB[(px + 4*i)*SROW + w];
        }
        #pragma unroll
        for (int i = 0; i < 4; i++)
            #pragma unroll
            for (int j = 0; j < 4; j++)
                acc[i*4+j] += __popc(a[i].x & b[j].x) + __popc(a[i].y & b[j].y)
                            + __popc(a[i].z & b[j].z) + __popc(a[i].w & b[j].w);
    }
    __syncthreads();
    int* sRed = (int*)sA;
    #pragma unroll
    for (int i = 0; i < 4; i++)
        #pragma unroll
        for (int j = 0; j < 4; j++)
            sRed[ws*256 + (qx + 4*i)*16 + (px + 4*j)] = acc[i*4+j];
    __syncthreads();
    int s = 0;
    #pragma unroll
    for (int k = 0; k < 16; k++) s += sRed[k*256 + t];
    atomicAdd(&g_inter1[(q0 + (t >> 4))*NQ + p0 + (t & 15)], s);
}

// ---------------- parallel argmax: one warp per q (first-index tie-break) ----------------
__global__ void match_kernel(int round){
    int q = blockIdx.x*8 + (threadIdx.x >> 5);
    int lane = threadIdx.x & 31;
    const int* inter = round ? g_inter2 : g_inter1;
    const int* cb    = g_cnt + (round ? 2*NQ : NQ);
    float ca = (float)(round ? g_cnt2[q] : g_cnt[q]);
    float best = -1.0f; int bi = 0;
    #pragma unroll
    for (int k = 0; k < 2; k++){
        int p = lane + k*32;
        float in = (float)inter[q*NQ + p];
        float un = ca + (float)cb[p] - in;
        float io = in / fmaxf(un, 1.0f);
        if (io > best){ best = io; bi = p; }
    }
    #pragma unroll
    for (int d = 16; d; d >>= 1){
        float ob = __shfl_xor_sync(~0u, best, d);
        int   oi = __shfl_xor_sync(~0u, bi,   d);
        if (ob > best || (ob == best && oi < bi)){ best = ob; bi = oi; }
    }
    if (lane == 0){
        if (round == 0){
            g_idx1[q] = bi; g_m1[q] = best > IOU_T; g_iou1[q] = best;
        } else {
            g_idx2[q] = bi; g_m2[q] = best > IOU_T;
            g_keep[q] = ((g_iou1[q] + best) * 0.5f) > IOU_T;
        }
    }
}

// ---------------- pass 2 FUSED: merged anchor + fp16 a1 + inline inter2 vs s2 ----------------
// grid (NN4/1024, NQ); each warp accumulates popc(word & s2[p][w]) for p=lane, lane+32
__global__ void mask2_inter_kernel(const float4* __restrict__ vl4){
    int q = blockIdx.y;
    int t = threadIdx.x, lane = t & 31, warp = t >> 5;
    int p1 = g_idx1[q], m = g_m1[q];
    size_t r0 = (size_t)q * NN4;
    size_t r1 = (size_t)(NQ + p1) * NN4;
    const unsigned* S2 = g_mask + (size_t)2*NQ*NW;   // L2-resident (4.2 MB)
    int wbase = blockIdx.x * 128;
    int acc_lo = 0, acc_hi = 0, cnt = 0;
    #pragma unroll
    for (int j = 0; j < 4; j++){
        int f = blockIdx.x*1024 + j*256 + t;
        float4 v0 = __ldcs(&vl4[r0 + f]);
        float4 a;
        a.x = sigf(v0.x); a.y = sigf(v0.y); a.z = sigf(v0.z); a.w = sigf(v0.w);
        if (m){
            float4 v1 = __ldcs(&vl4[r1 + f]);
            a.x = (a.x + sigf(v1.x)) * 0.5f;
            a.y = (a.y + sigf(v1.y)) * 0.5f;
            a.z = (a.z + sigf(v1.z)) * 0.5f;
            a.w = (a.w + sigf(v1.w)) * 0.5f;
        }
        g_a1[(size_t)q*NN4 + f] = pack4h(a.x, a.y, a.z, a.w);
        unsigned nib = (unsigned)(a.x > 0.5f) | ((unsigned)(a.y > 0.5f) << 1)
                     | ((unsigned)(a.z > 0.5f) << 2) | ((unsigned)(a.w > 0.5f) << 3);
        unsigned part = nib << ((lane & 7) * 4);
        part |= __shfl_xor_sync(~0u, part, 1);
        part |= __shfl_xor_sync(~0u, part, 2);
        part |= __shfl_xor_sync(~0u, part, 4);   // full word on every lane of its 8-lane group
        if ((lane & 7) == 0) cnt += __popc(part);
        int wrow = wbase + j*32 + warp*4;        // word index of group 0
        #pragma unroll
        for (int g = 0; g < 4; g++){
            unsigned wd = __shfl_sync(~0u, part, g*8);
            int w = wrow + g;
            acc_lo += __popc(wd & __ldg(&S2[(size_t)lane*NW + w]));
            acc_hi += __popc(wd & __ldg(&S2[(size_t)(lane+32)*NW + w]));
        }
    }
    // block reductions
    __shared__ int sAcc[8][64];
    __shared__ int sCnt[8];
    sAcc[warp][lane]      = acc_lo;
    sAcc[warp][lane + 32] = acc_hi;
    #pragma unroll
    for (int d = 16; d; d >>= 1) cnt += __shfl_xor_sync(~0u, cnt, d);
    if (lane == 0) sCnt[warp] = cnt;
    __syncthreads();
    if (t < 64){
        int s = 0;
        #pragma unroll
        for (int k = 0; k < 8; k++) s += sAcc[k][t];
        atomicAdd(&g_inter2[q*NQ + t], s);
    }
    if (t == 64){
        int s = 0;
        #pragma unroll
        for (int k = 0; k < 8; k++) s += sCnt[k];
        atomicAdd(&g_cnt2[q], s);
    }
}

// ---------------- pass 3: final output ----------------
__global__ void out_kernel(const float4* __restrict__ vl4, float4* __restrict__ out4){
    int q = blockIdx.y;
    int t = threadIdx.x;
    size_t orow4 = (size_t)q * NN4;
    int keep = g_keep[q];
    int m2 = g_m2[q];
    size_t r2 = (size_t)(2*NQ + g_idx2[q]) * NN4;
    #pragma unroll
    for (int j = 0; j < 4; j++){
        int f = blockIdx.x*1024 + j*256 + t;
        float4 o = make_float4(0.f, 0.f, 0.f, 0.f);
        if (keep){
            float4 a = unpack4h(g_a1[(size_t)q*NN4 + f]);   // mostly L2-hit
            if (m2){
                float4 v2 = __ldcs(&vl4[r2 + f]);
                a.x = (a.x*2.f + sigf(v2.x)) * (1.f/3.f);
                a.y = (a.y*2.f + sigf(v2.y)) * (1.f/3.f);
                a.z = (a.z*2.f + sigf(v2.z)) * (1.f/3.f);
                a.w = (a.w*2.f + sigf(v2.w)) * (1.f/3.f);
            }
            unsigned ob = g_occ[f >> 3] >> ((f & 7) * 4);
            o.x = (ob & 1u) ? a.x : 0.f;
            o.y = (ob & 2u) ? a.y : 0.f;
            o.z = (ob & 4u) ? a.z : 0.f;
            o.w = (ob & 8u) ? a.w : 0.f;
        }
        __stcs(&out4[orow4 + f], o);
    }
}

// ---------------- launch ----------------
extern "C" void kernel_launch(void* const* d_in, const int* in_sizes, int n_in,
                              void* d_out, int out_size){
    const float4* vl4  = (const float4*)d_in[0];   // voxel_logits [3,64,128,128,32]
    const float4* sem4 = (const float4*)d_in[2];   // sem_prob_dense [21,128,128,32]
    float4* out4 = (float4*)d_out;                 // [64,128,128,32]

    static cudaStream_t s1 = 0;
    static cudaEvent_t evA = 0, evB = 0, evC = 0;
    static int initd = 0;
    if (!initd){
        if (cudaStreamCreateWithFlags(&s1, cudaStreamNonBlocking) != cudaSuccess) s1 = 0;
        cudaEventCreateWithFlags(&evA, cudaEventDisableTiming);
        cudaEventCreateWithFlags(&evB, cudaEventDisableTiming);
        cudaEventCreateWithFlags(&evC, cudaEventDisableTiming);
        initd = 1;
    }

    init_kernel <<< 16, 256 >>> ();

    if (s1){
        mask_kernel <<< dim3(NN4/1024, NQ, 2), 256 >>> (vl4, 0, 0);   // s=0,1 (main)
        cudaEventRecord(evA, 0);
        // side: mask s=2 (with row counts) + occ; overlaps inter0/match windows
        cudaStreamWaitEvent(s1, evA, 0);
        mask_kernel <<< dim3(NN4/1024, NQ, 1), 256, 0, s1 >>> (vl4, 2, 1);
        cudaEventRecord(evB, s1);
        occ_kernel  <<< NN4/256, 256, 0, s1 >>> (sem4);
        cudaEventRecord(evC, s1);

        inter_kernel<<< dim3(NW/WCH, 4, 4), 256 >>> ();
        match_kernel<<< 8, 256 >>> (0);
        cudaStreamWaitEvent(0, evB, 0);    // fused kernel reads s2 bits
        mask2_inter_kernel<<< dim3(NN4/1024, NQ), 256 >>> (vl4);
        match_kernel<<< 8, 256 >>> (1);
        cudaStreamWaitEvent(0, evC, 0);    // occ ready for out
        out_kernel  <<< dim3(NN4/1024, NQ), 256 >>> (vl4, out4);
    } else {
        mask_kernel <<< dim3(NN4/1024, NQ, 3), 256 >>> (vl4, 0, 1);
        occ_kernel  <<< NN4/256, 256 >>> (sem4);
        inter_kernel<<< dim3(NW/WCH, 4, 4), 256 >>> ();
        match_kernel<<< 8, 256 >>> (0);
        mask2_inter_kernel<<< dim3(NN4/1024, NQ), 256 >>> (vl4);
        match_kernel<<< 8, 256 >>> (1);
        out_kernel  <<< dim3(NN4/1024, NQ), 256 >>> (vl4, out4);
    }
}

// round 10
// speedup vs baseline: 1.5123x; 1.5123x over previous
#include <cuda_runtime.h>
#include <cuda_fp16.h>

#define NS 3
#define NQ 64
#define NN (128*128*32)    // 524288
#define NN4 (NN/4)         // 131072 float4 per row
#define NW (NN/32)         // 16384 packed words per row
#define NC 21
#define IOU_T 0.2f
#define WCH 256
#define SROW (WCH+4)       // 260-word smem row stride

#define NB_INTER 1024      // (NW/WCH)*16 tiles
#define NB_MASK2S 8192     // 128 xblocks * 64 q  (s=2 mask)
#define NB_OCC 512
#define NB_FUSED (NB_INTER + NB_MASK2S + NB_OCC)   // 9728 = 512*19

// ---------------- scratch (device globals; no allocation) ----------------
__device__ unsigned g_mask [NS*NQ*NW];
__device__ unsigned g_mask2[NQ*NW];
__device__ unsigned g_occ  [NW];
__device__ uint2    g_a1   [(size_t)NQ*NN4];   // merged anchor after iter1, fp16x4 (output path only)
__device__ int g_cnt [NS*NQ];
__device__ int g_cnt2[NQ];
__device__ int g_inter1[NQ*NQ];
__device__ int g_inter2[NQ*NQ];
__device__ int g_idx1[NQ], g_m1[NQ], g_idx2[NQ], g_m2[NQ], g_keep[NQ];
__device__ float g_iou1[NQ];

__device__ __forceinline__ float sigf(float x){ return 1.0f/(1.0f + __expf(-x)); }

__device__ __forceinline__ uint2 pack4h(float a, float b, float c, float d){
    __half2 h01 = __floats2half2_rn(a, b);
    __half2 h23 = __floats2half2_rn(c, d);
    uint2 r; r.x = *(unsigned*)&h01; r.y = *(unsigned*)&h23; return r;
}
__device__ __forceinline__ float4 unpack4h(uint2 hv){
    float2 a01 = __half22float2(*(__half2*)&hv.x);
    float2 a23 = __half22float2(*(__half2*)&hv.y);
    return make_float4(a01.x, a01.y, a23.x, a23.y);
}

// ---------------- zero accumulators ----------------
__global__ void init_kernel(){
    int t = blockIdx.x*256 + threadIdx.x;
    if (t < NQ*NQ){ g_inter1[t] = 0; g_inter2[t] = 0; }
    if (t < NS*NQ) g_cnt[t] = 0;
    if (t < NQ)    g_cnt2[t] = 0;
}

// ---------------- pass 1: pack (logit>0) bits, s=0,1 — pure stream ----------------
__global__ void mask_kernel(const float4* __restrict__ vl4){
    int s = blockIdx.z, q = blockIdx.y;
    int row = s*NQ + q;
    size_t row4 = (size_t)row * NN4;
    size_t mrow = (size_t)row * NW;
    int t = threadIdx.x, lane = t & 31;
    #pragma unroll
    for (int j = 0; j < 4; j++){
        int f = blockIdx.x*1024 + j*256 + t;
        float4 v = __ldcs(&vl4[row4 + f]);
        unsigned nib = (unsigned)(v.x > 0.f) | ((unsigned)(v.y > 0.f) << 1)
                     | ((unsigned)(v.z > 0.f) << 2) | ((unsigned)(v.w > 0.f) << 3);
        unsigned part = nib << ((lane & 7) * 4);
        part |= __shfl_xor_sync(~0u, part, 1);
        part |= __shfl_xor_sync(~0u, part, 2);
        part |= __shfl_xor_sync(~0u, part, 4);
        if ((lane & 7) == 0) g_mask[mrow + (f >> 3)] = part;
    }
}

// ---------------- inter body (R6-proven 4x4 tile; used by fused + round1) ----------------
__device__ __forceinline__ void inter_body(
    unsigned* sA, unsigned* sB,
    const unsigned* A, const unsigned* B, int* inter, int* cntA, int* cntB,
    int wc, int q0, int p0)
{
    int w0 = wc * WCH;
    int t = threadIdx.x;
    for (int i = t; i < 16*64; i += 256){
        int r = i >> 6, c = (i & 63) * 4;
        *(uint4*)&sA[r*SROW + c] = *(const uint4*)&A[(size_t)(q0 + r)*NW + w0 + c];
        *(uint4*)&sB[r*SROW + c] = *(const uint4*)&B[(size_t)(p0 + r)*NW + w0 + c];
    }
    __syncthreads();
    if (p0 == 0){
        int r = t >> 4, part = t & 15;
        int c = 0;
        #pragma unroll
        for (int w = 0; w < 16; w++) c += __popc(sA[r*SROW + part*16 + w]);
        #pragma unroll
        for (int d = 8; d; d >>= 1) c += __shfl_down_sync(~0u, c, d, 16);
        if (part == 0) atomicAdd(&cntA[q0 + r], c);
    }
    if (q0 == 0){
        int r = t >> 4, part = t & 15;
        int c = 0;
        #pragma unroll
        for (int w = 0; w < 16; w++) c += __popc(sB[r*SROW + part*16 + w]);
        #pragma unroll
        for (int d = 8; d; d >>= 1) c += __shfl_down_sync(~0u, c, d, 16);
        if (part == 0) atomicAdd(&cntB[p0 + r], c);
    }
    int px = t & 3, qx = (t >> 2) & 3, ws = t >> 4;
    int acc[16];
    #pragma unroll
    for (int k = 0; k < 16; k++) acc[k] = 0;
    int wbeg = ws * 16;
    #pragma unroll
    for (int w = wbeg; w < wbeg + 16; w += 4){
        uint4 a[4], b[4];
        #pragma unroll
        for (int i = 0; i < 4; i++){
            a[i] = *(uint4*)&sA[(qx + 4*i)*SROW + w];
            b[i] = *(uint4*)&sB[(px + 4*i)*SROW + w];
        }
        #pragma unroll
        for (int i = 0; i < 4; i++)
            #pragma unroll
            for (int j = 0; j < 4; j++)
                acc[i*4+j] += __popc(a[i].x & b[j].x) + __popc(a[i].y & b[j].y)
                            + __popc(a[i].z & b[j].z) + __popc(a[i].w & b[j].w);
    }
    __syncthreads();
    int* sRed = (int*)sA;
    #pragma unroll
    for (int i = 0; i < 4; i++)
        #pragma unroll
        for (int j = 0; j < 4; j++)
            sRed[ws*256 + (qx + 4*i)*16 + (px + 4*j)] = acc[i*4+j];
    __syncthreads();
    int s = 0;
    #pragma unroll
    for (int k = 0; k < 16; k++) s += sRed[k*256 + t];
    atomicAdd(&inter[(q0 + (t >> 4))*NQ + p0 + (t & 15)], s);
}

// ---------------- FUSED: inter0 (ALU) + mask s=2 + occ (DRAM), block-interleaved ----------------
__global__ void __launch_bounds__(256, 4) fused0_kernel(
    const float4* __restrict__ vl4, const float4* __restrict__ sem4)
{
    __shared__ unsigned sA[16*SROW];
    __shared__ unsigned sB[16*SROW];
    int bid = blockIdx.x;
    int r19 = bid % 19, g19 = bid / 19;
    int t = threadIdx.x, lane = t & 31;

    if (r19 < 2){
        // ---- inter round 0: s0 x s1 + fused row counts ----
        int ib = g19*2 + r19;                 // 0..1023
        int wc = ib & 63;
        int q0 = ((ib >> 6) & 3) * 16;
        int p0 = (ib >> 8) * 16;
        inter_body(sA, sB, g_mask, g_mask + (size_t)NQ*NW,
                   g_inter1, g_cnt, g_cnt + NQ, wc, q0, p0);
        return;
    }
    int sbid = g19*17 + (r19 - 2);            // 0..8703
    if (sbid < NB_MASK2S){
        // ---- mask s=2 ----
        int q = sbid >> 7, xb = sbid & 127;
        int row = 2*NQ + q;
        size_t row4 = (size_t)row * NN4;
        size_t mrow = (size_t)row * NW;
        #pragma unroll
        for (int j = 0; j < 4; j++){
            int f = xb*1024 + j*256 + t;
            float4 v = __ldcs(&vl4[row4 + f]);
            unsigned nib = (unsigned)(v.x > 0.f) | ((unsigned)(v.y > 0.f) << 1)
                         | ((unsigned)(v.z > 0.f) << 2) | ((unsigned)(v.w > 0.f) << 3);
            unsigned part = nib << ((lane & 7) * 4);
            part |= __shfl_xor_sync(~0u, part, 1);
            part |= __shfl_xor_sync(~0u, part, 2);
            part |= __shfl_xor_sync(~0u, part, 4);
            if ((lane & 7) == 0) g_mask[mrow + (f >> 3)] = part;
        }
    } else {
        // ---- occupancy bits ----
        int f = (sbid - NB_MASK2S)*256 + t;
        float4 v0 = __ldcs(&sem4[f]);
        unsigned nib = 0;
        #pragma unroll
        for (int c = 1; c < NC; c++){
            float4 vc = __ldcs(&sem4[(size_t)c*NN4 + f]);
            nib |= (unsigned)(vc.x > v0.x) | ((unsigned)(vc.y > v0.y) << 1)
                 | ((unsigned)(vc.z > v0.z) << 2) | ((unsigned)(vc.w > v0.w) << 3);
        }
        unsigned part = nib << ((lane & 7) * 4);
        part |= __shfl_xor_sync(~0u, part, 1);
        part |= __shfl_xor_sync(~0u, part, 2);
        part |= __shfl_xor_sync(~0u, part, 4);
        if ((lane & 7) == 0) g_occ[f >> 3] = part;
    }
}

// ---------------- inter round 1: mask2 x s2 ----------------
__global__ void __launch_bounds__(256, 4) inter1_kernel(){
    __shared__ unsigned sA[16*SROW];
    __shared__ unsigned sB[16*SROW];
    inter_body(sA, sB, g_mask2, g_mask + (size_t)2*NQ*NW,
               g_inter2, g_cnt2, g_cnt + 2*NQ,
               blockIdx.x, blockIdx.y*16, blockIdx.z*16);
}

// ---------------- parallel argmax: one warp per q (first-index tie-break) ----------------
__global__ void match_kernel(int round){
    int q = blockIdx.x*8 + (threadIdx.x >> 5);
    int lane = threadIdx.x & 31;
    const int* inter = round ? g_inter2 : g_inter1;
    const int* cb    = g_cnt + (round ? 2*NQ : NQ);
    float ca = (float)(round ? g_cnt2[q] : g_cnt[q]);
    float best = -1.0f; int bi = 0;
    #pragma unroll
    for (int k = 0; k < 2; k++){
        int p = lane + k*32;
        float in = (float)inter[q*NQ + p];
        float un = ca + (float)cb[p] - in;
        float io = in / fmaxf(un, 1.0f);
        if (io > best){ best = io; bi = p; }
    }
    #pragma unroll
    for (int d = 16; d; d >>= 1){
        float ob = __shfl_xor_sync(~0u, best, d);
        int   oi = __shfl_xor_sync(~0u, bi,   d);
        if (ob > best || (ob == best && oi < bi)){ best = ob; bi = oi; }
    }
    if (lane == 0){
        if (round == 0){
            g_idx1[q] = bi; g_m1[q] = best > IOU_T; g_iou1[q] = best;
        } else {
            g_idx2[q] = bi; g_m2[q] = best > IOU_T;
            g_keep[q] = ((g_iou1[q] + best) * 0.5f) > IOU_T;
        }
    }
}

// ---------------- pass 2: merged anchor (fp32-exact bits) + fp16 a1 ----------------
__global__ void mask2_kernel(const float4* __restrict__ vl4){
    int q = blockIdx.y;
    int t = threadIdx.x, lane = t & 31;
    int p = g_idx1[q], m = g_m1[q];
    size_t r0 = (size_t)q * NN4;
    size_t r1 = (size_t)(NQ + p) * NN4;
    #pragma unroll
    for (int j = 0; j < 4; j++){
        int f = blockIdx.x*1024 + j*256 + t;
        float4 v0 = __ldcs(&vl4[r0 + f]);
        float4 a;
        a.x = sigf(v0.x); a.y = sigf(v0.y); a.z = sigf(v0.z); a.w = sigf(v0.w);
        if (m){
            float4 v1 = __ldcs(&vl4[r1 + f]);
            a.x = (a.x + sigf(v1.x)) * 0.5f;
            a.y = (a.y + sigf(v1.y)) * 0.5f;
            a.z = (a.z + sigf(v1.z)) * 0.5f;
            a.w = (a.w + sigf(v1.w)) * 0.5f;
        }
        g_a1[(size_t)q*NN4 + f] = pack4h(a.x, a.y, a.z, a.w);
        unsigned nib = (unsigned)(a.x > 0.5f) | ((unsigned)(a.y > 0.5f) << 1)
                     | ((unsigned)(a.z > 0.5f) << 2) | ((unsigned)(a.w > 0.5f) << 3);
        unsigned part = nib << ((lane & 7) * 4);
        part |= __shfl_xor_sync(~0u, part, 1);
        part |= __shfl_xor_sync(~0u, part, 2);
        part |= __shfl_xor_sync(~0u, part, 4);
        if ((lane & 7) == 0) g_mask2[(size_t)q*NW + (f >> 3)] = part;
    }
}

// ---------------- pass 3: final output ----------------
__global__ void out_kernel(const float4* __restrict__ vl4, float4* __restrict__ out4){
    int q = blockIdx.y;
    int t = threadIdx.x;
    size_t orow4 = (size_t)q * NN4;
    int keep = g_keep[q];
    int m2 = g_m2[q];
    size_t r2 = (size_t)(2*NQ + g_idx2[q]) * NN4;
    #pragma unroll
    for (int j = 0; j < 4; j++){
        int f = blockIdx.x*1024 + j*256 + t;
        float4 o = make_float4(0.f, 0.f, 0.f, 0.f);
        if (keep){
            float4 a = unpack4h(g_a1[(size_t)q*NN4 + f]);   // mostly L2-hit
            if (m2){
                float4 v2 = __ldcs(&vl4[r2 + f]);
                a.x = (a.x*2.f + sigf(v2.x)) * (1.f/3.f);
                a.y = (a.y*2.f + sigf(v2.y)) * (1.f/3.f);
                a.z = (a.z*2.f + sigf(v2.z)) * (1.f/3.f);
                a.w = (a.w*2.f + sigf(v2.w)) * (1.f/3.f);
            }
            unsigned ob = g_occ[f >> 3] >> ((f & 7) * 4);
            o.x = (ob & 1u) ? a.x : 0.f;
            o.y = (ob & 2u) ? a.y : 0.f;
            o.z = (ob & 4u) ? a.z : 0.f;
            o.w = (ob & 8u) ? a.w : 0.f;
        }
        __stcs(&out4[orow4 + f], o);
    }
}

// ---------------- launch: single stream, co-residency via fused kernel ----------------
extern "C" void kernel_launch(void* const* d_in, const int* in_sizes, int n_in,
                              void* d_out, int out_size){
    const float4* vl4  = (const float4*)d_in[0];   // voxel_logits [3,64,128,128,32]
    const float4* sem4 = (const float4*)d_in[2];   // sem_prob_dense [21,128,128,32]
    float4* out4 = (float4*)d_out;                 // [64,128,128,32]

    init_kernel  <<< 16, 256 >>> ();
    mask_kernel  <<< dim3(NN4/1024, NQ, 2), 256 >>> (vl4);     // s=0,1
    fused0_kernel<<< NB_FUSED, 256 >>> (vl4, sem4);            // inter0 + mask s=2 + occ
    match_kernel <<< 8, 256 >>> (0);
    mask2_kernel <<< dim3(NN4/1024, NQ), 256 >>> (vl4);
    inter1_kernel<<< dim3(NW/WCH, 4, 4), 256 >>> ();
    match_kernel <<< 8, 256 >>> (1);
    out_kernel   <<< dim3(NN4/1024, NQ), 256 >>> (vl4, out4);
}

// round 11
// speedup vs baseline: 1.5832x; 1.0469x over previous
#include <cuda_runtime.h>
#include <cuda_fp16.h>

#define NS 3
#define NQ 64
#define NN (128*128*32)    // 524288
#define NN4 (NN/4)         // 131072 float4 per row
#define NW (NN/32)         // 16384 packed words per row
#define NC 21
#define IOU_T 0.2f
#define WCH 256
#define SROW (WCH+4)       // 260-word smem row stride

// ---------------- scratch (device globals; no allocation) ----------------
__device__ unsigned g_mask [NS*NQ*NW];
__device__ unsigned g_mask2[NQ*NW];
__device__ unsigned g_occ  [NW];
__device__ uint2    g_a1   [(size_t)NQ*NN4];   // merged anchor after iter1, fp16x4 (output path only)
__device__ int g_cnt [NS*NQ];
__device__ int g_cnt2[NQ];
__device__ int g_inter1[NQ*NQ];
__device__ int g_inter2[NQ*NQ];
__device__ int g_idx1[NQ], g_m1[NQ], g_idx2[NQ], g_m2[NQ], g_keep[NQ];
__device__ float g_iou1[NQ];

__device__ __forceinline__ float sigf(float x){ return 1.0f/(1.0f + __expf(-x)); }

__device__ __forceinline__ uint2 pack4h(float a, float b, float c, float d){
    __half2 h01 = __floats2half2_rn(a, b);
    __half2 h23 = __floats2half2_rn(c, d);
    uint2 r; r.x = *(unsigned*)&h01; r.y = *(unsigned*)&h23; return r;
}
__device__ __forceinline__ float4 unpack4h(uint2 hv){
    float2 a01 = __half22float2(*(__half2*)&hv.x);
    float2 a23 = __half22float2(*(__half2*)&hv.y);
    return make_float4(a01.x, a01.y, a23.x, a23.y);
}

// ---------------- zero accumulators ----------------
__global__ void init_kernel(){
    int t = blockIdx.x*256 + threadIdx.x;
    if (t < NQ*NQ){ g_inter1[t] = 0; g_inter2[t] = 0; }
    if (t < NS*NQ) g_cnt[t] = 0;
    if (t < NQ)    g_cnt2[t] = 0;
}

// ---------------- occupancy bits (pure streaming) ----------------
__global__ void occ_kernel(const float4* __restrict__ sem4){
    int f = blockIdx.x*256 + threadIdx.x;
    int lane = threadIdx.x & 31;
    float4 v0 = __ldcs(&sem4[f]);
    unsigned nib = 0;
    #pragma unroll
    for (int c = 1; c < NC; c++){
        float4 vc = __ldcs(&sem4[(size_t)c*NN4 + f]);
        nib |= (unsigned)(vc.x > v0.x) | ((unsigned)(vc.y > v0.y) << 1)
             | ((unsigned)(vc.z > v0.z) << 2) | ((unsigned)(vc.w > v0.w) << 3);
    }
    unsigned part = nib << ((lane & 7) * 4);
    part |= __shfl_xor_sync(~0u, part, 1);
    part |= __shfl_xor_sync(~0u, part, 2);
    part |= __shfl_xor_sync(~0u, part, 4);
    if ((lane & 7) == 0) g_occ[f >> 3] = part;
}

// ---------------- pass 1: pack (logit>0) bits — pure stream ----------------
__global__ void mask_kernel(const float4* __restrict__ vl4, int s_base){
    int s = blockIdx.z + s_base, q = blockIdx.y;
    int row = s*NQ + q;
    size_t row4 = (size_t)row * NN4;
    size_t mrow = (size_t)row * NW;
    int t = threadIdx.x, lane = t & 31;
    #pragma unroll
    for (int j = 0; j < 4; j++){
        int f = blockIdx.x*1024 + j*256 + t;
        float4 v = __ldcs(&vl4[row4 + f]);
        unsigned nib = (unsigned)(v.x > 0.f) | ((unsigned)(v.y > 0.f) << 1)
                     | ((unsigned)(v.z > 0.f) << 2) | ((unsigned)(v.w > 0.f) << 3);
        unsigned part = nib << ((lane & 7) * 4);
        part |= __shfl_xor_sync(~0u, part, 1);
        part |= __shfl_xor_sync(~0u, part, 2);
        part |= __shfl_xor_sync(~0u, part, 4);
        if ((lane & 7) == 0) g_mask[mrow + (f >> 3)] = part;
    }
}

// ---------------- bit-popcount GEMM + fused row counts (R6 body; 3 blocks/SM) ----------------
__global__ void __launch_bounds__(256, 3) inter_kernel(int round){
    __shared__ unsigned sA[16*SROW];
    __shared__ unsigned sB[16*SROW];
    const unsigned* A = round ? g_mask2 : g_mask;
    const unsigned* B = g_mask + (size_t)(round ? 2 : 1) * NQ * NW;
    int* inter = round ? g_inter2 : g_inter1;
    int* cntA  = round ? g_cnt2 : g_cnt;
    int* cntB  = g_cnt + (round ? 2 : 1) * NQ;
    int w0 = blockIdx.x * WCH;
    int q0 = blockIdx.y * 16, p0 = blockIdx.z * 16;
    int t = threadIdx.x;
    for (int i = t; i < 16*64; i += 256){
        int r = i >> 6, c = (i & 63) * 4;
        *(uint4*)&sA[r*SROW + c] = *(const uint4*)&A[(size_t)(q0 + r)*NW + w0 + c];
        *(uint4*)&sB[r*SROW + c] = *(const uint4*)&B[(size_t)(p0 + r)*NW + w0 + c];
    }
    __syncthreads();
    if (blockIdx.z == 0){
        int r = t >> 4, part = t & 15;
        int c = 0;
        #pragma unroll
        for (int w = 0; w < 16; w++) c += __popc(sA[r*SROW + part*16 + w]);
        #pragma unroll
        for (int d = 8; d; d >>= 1) c += __shfl_down_sync(~0u, c, d, 16);
        if (part == 0) atomicAdd(&cntA[q0 + r], c);
    }
    if (blockIdx.y == 0){
        int r = t >> 4, part = t & 15;
        int c = 0;
        #pragma unroll
        for (int w = 0; w < 16; w++) c += __popc(sB[r*SROW + part*16 + w]);
        #pragma unroll
        for (int d = 8; d; d >>= 1) c += __shfl_down_sync(~0u, c, d, 16);
        if (part == 0) atomicAdd(&cntB[p0 + r], c);
    }
    int px = t & 3, qx = (t >> 2) & 3, ws = t >> 4;
    int acc[16];
    #pragma unroll
    for (int k = 0; k < 16; k++) acc[k] = 0;
    int wbeg = ws * 16;
    #pragma unroll
    for (int w = wbeg; w < wbeg + 16; w += 4){
        uint4 a[4], b[4];
        #pragma unroll
        for (int i = 0; i < 4; i++){
            a[i] = *(uint4*)&sA[(qx + 4*i)*SROW + w];
            b[i] = *(uint4*)&sB[(px + 4*i)*SROW + w];
        }
        #pragma unroll
        for (int i = 0; i < 4; i++)
            #pragma unroll
            for (int j = 0; j < 4; j++)
                acc[i*4+j] += __popc(a[i].x & b[j].x) + __popc(a[i].y & b[j].y)
                            + __popc(a[i].z & b[j].z) + __popc(a[i].w & b[j].w);
    }
    __syncthreads();
    int* sRed = (int*)sA;
    #pragma unroll
    for (int i = 0; i < 4; i++)
        #pragma unroll
        for (int j = 0; j < 4; j++)
            sRed[ws*256 + (qx + 4*i)*16 + (px + 4*j)] = acc[i*4+j];
    __syncthreads();
    int s = 0;
    #pragma unroll
    for (int k = 0; k < 16; k++) s += sRed[k*256 + t];
    atomicAdd(&inter[(q0 + (t >> 4))*NQ + p0 + (t & 15)], s);
}

// ---------------- parallel argmax: one warp per q (first-index tie-break) ----------------
__global__ void match_kernel(int round){
    int q = blockIdx.x*8 + (threadIdx.x >> 5);
    int lane = threadIdx.x & 31;
    const int* inter = round ? g_inter2 : g_inter1;
    const int* cb    = g_cnt + (round ? 2*NQ : NQ);
    float ca = (float)(round ? g_cnt2[q] : g_cnt[q]);
    float best = -1.0f; int bi = 0;
    #pragma unroll
    for (int k = 0; k < 2; k++){
        int p = lane + k*32;
        float in = (float)inter[q*NQ + p];
        float un = ca + (float)cb[p] - in;
        float io = in / fmaxf(un, 1.0f);
        if (io > best){ best = io; bi = p; }
    }
    #pragma unroll
    for (int d = 16; d; d >>= 1){
        float ob = __shfl_xor_sync(~0u, best, d);
        int   oi = __shfl_xor_sync(~0u, bi,   d);
        if (ob > best || (ob == best && oi < bi)){ best = ob; bi = oi; }
    }
    if (lane == 0){
        if (round == 0){
            g_idx1[q] = bi; g_m1[q] = best > IOU_T; g_iou1[q] = best;
        } else {
            g_idx2[q] = bi; g_m2[q] = best > IOU_T;
            g_keep[q] = ((g_iou1[q] + best) * 0.5f) > IOU_T;
        }
    }
}

// ---------------- pass 2: merged anchor (fp32-exact bits) + fp16 a1 ----------------
__global__ void mask2_kernel(const float4* __restrict__ vl4){
    int q = blockIdx.y;
    int t = threadIdx.x, lane = t & 31;
    int p = g_idx1[q], m = g_m1[q];
    size_t r0 = (size_t)q * NN4;
    size_t r1 = (size_t)(NQ + p) * NN4;
    #pragma unroll
    for (int j = 0; j < 4; j++){
        int f = blockIdx.x*1024 + j*256 + t;
        float4 v0 = __ldcs(&vl4[r0 + f]);
        float4 a;
        a.x = sigf(v0.x); a.y = sigf(v0.y); a.z = sigf(v0.z); a.w = sigf(v0.w);
        if (m){
            float4 v1 = __ldcs(&vl4[r1 + f]);
            a.x = (a.x + sigf(v1.x)) * 0.5f;
            a.y = (a.y + sigf(v1.y)) * 0.5f;
            a.z = (a.z + sigf(v1.z)) * 0.5f;
            a.w = (a.w + sigf(v1.w)) * 0.5f;
        }
        g_a1[(size_t)q*NN4 + f] = pack4h(a.x, a.y, a.z, a.w);
        unsigned nib = (unsigned)(a.x > 0.5f) | ((unsigned)(a.y > 0.5f) << 1)
                     | ((unsigned)(a.z > 0.5f) << 2) | ((unsigned)(a.w > 0.5f) << 3);
        unsigned part = nib << ((lane & 7) * 4);
        part |= __shfl_xor_sync(~0u, part, 1);
        part |= __shfl_xor_sync(~0u, part, 2);
        part |= __shfl_xor_sync(~0u, part, 4);
        if ((lane & 7) == 0) g_mask2[(size_t)q*NW + (f >> 3)] = part;
    }
}

// ---------------- pass 3: final output ----------------
__global__ void out_kernel(const float4* __restrict__ vl4, float4* __restrict__ out4){
    int q = blockIdx.y;
    int t = threadIdx.x;
    size_t orow4 = (size_t)q * NN4;
    int keep = g_keep[q];
    int m2 = g_m2[q];
    size_t r2 = (size_t)(2*NQ + g_idx2[q]) * NN4;
    #pragma unroll
    for (int j = 0; j < 4; j++){
        int f = blockIdx.x*1024 + j*256 + t;
        float4 o = make_float4(0.f, 0.f, 0.f, 0.f);
        if (keep){
            float4 a = unpack4h(g_a1[(size_t)q*NN4 + f]);   // mostly L2-hit
            if (m2){
                float4 v2 = __ldcs(&vl4[r2 + f]);
                a.x = (a.x*2.f + sigf(v2.x)) * (1.f/3.f);
                a.y = (a.y*2.f + sigf(v2.y)) * (1.f/3.f);
                a.z = (a.z*2.f + sigf(v2.z)) * (1.f/3.f);
                a.w = (a.w*2.f + sigf(v2.w)) * (1.f/3.f);
            }
            unsigned ob = g_occ[f >> 3] >> ((f & 7) * 4);
            o.x = (ob & 1u) ? a.x : 0.f;
            o.y = (ob & 2u) ? a.y : 0.f;
            o.z = (ob & 4u) ? a.z : 0.f;
            o.w = (ob & 8u) ? a.w : 0.f;
        }
        __stcs(&out4[orow4 + f], o);
    }
}

// ---------------- launch: inter on side stream, streaming work on main ----------------
extern "C" void kernel_launch(void* const* d_in, const int* in_sizes, int n_in,
                              void* d_out, int out_size){
    const float4* vl4  = (const float4*)d_in[0];   // voxel_logits [3,64,128,128,32]
    const float4* sem4 = (const float4*)d_in[2];   // sem_prob_dense [21,128,128,32]
    float4* out4 = (float4*)d_out;                 // [64,128,128,32]

    static cudaStream_t s1 = 0;
    static cudaEvent_t evA = 0, evI0 = 0, evM2 = 0, evI1 = 0;
    static int initd = 0;
    if (!initd){
        if (cudaStreamCreateWithFlags(&s1, cudaStreamNonBlocking) != cudaSuccess) s1 = 0;
        cudaEventCreateWithFlags(&evA,  cudaEventDisableTiming);
        cudaEventCreateWithFlags(&evI0, cudaEventDisableTiming);
        cudaEventCreateWithFlags(&evM2, cudaEventDisableTiming);
        cudaEventCreateWithFlags(&evI1, cudaEventDisableTiming);
        initd = 1;
    }

    init_kernel <<< 16, 256 >>> ();

    if (s1){
        // S0: mask01 (s=0,1) — inter0's inputs
        mask_kernel <<< dim3(NN4/1024, NQ, 2), 256 >>> (vl4, 0);
        cudaEventRecord(evA, 0);

        // S1: inter0 runs concurrent with S0's mask_s2
        cudaStreamWaitEvent(s1, evA, 0);
        inter_kernel<<< dim3(NW/WCH, 4, 4), 256, 0, s1 >>> (0);
        cudaEventRecord(evI0, s1);

        // S0: mask s=2 (DRAM work under inter0's ALU window)
        mask_kernel <<< dim3(NN4/1024, NQ, 1), 256 >>> (vl4, 2);

        // S0: match0 -> mask2
        cudaStreamWaitEvent(0, evI0, 0);
        match_kernel<<< 8, 256 >>> (0);
        mask2_kernel<<< dim3(NN4/1024, NQ), 256 >>> (vl4);
        cudaEventRecord(evM2, 0);

        // S1: inter1 concurrent with S0's occ
        cudaStreamWaitEvent(s1, evM2, 0);
        inter_kernel<<< dim3(NW/WCH, 4, 4), 256, 0, s1 >>> (1);
        cudaEventRecord(evI1, s1);

        // S0: occ (DRAM work under inter1's ALU window)
        occ_kernel  <<< NN4/256, 256 >>> (sem4);

        cudaStreamWaitEvent(0, evI1, 0);
        match_kernel<<< 8, 256 >>> (1);
        out_kernel  <<< dim3(NN4/1024, NQ), 256 >>> (vl4, out4);
    } else {
        mask_kernel <<< dim3(NN4/1024, NQ, 3), 256 >>> (vl4, 0);
        occ_kernel  <<< NN4/256, 256 >>> (sem4);
        inter_kernel<<< dim3(NW/WCH, 4, 4), 256 >>> (0);
        match_kernel<<< 8, 256 >>> (0);
        mask2_kernel<<< dim3(NN4/1024, NQ), 256 >>> (vl4);
        inter_kernel<<< dim3(NW/WCH, 4, 4), 256 >>> (1);
        match_kernel<<< 8, 256 >>> (1);
        out_kernel  <<< dim3(NN4/1024, NQ), 256 >>> (vl4, out4);
    }
}